// round 1
// baseline (speedup 1.0000x reference)
#include <cuda_runtime.h>

#define T_DATA 20000
#define E_NO   2000
#define I_NO   500
#define SUB    12
#define NTAP   200

// ---------------- device scratch (static, no allocation) ----------------
__device__ unsigned g_mask_e[SUB][64];   // [s][it*4+c], bit l <-> element it*128 + l*4 + c
__device__ unsigned g_mask_i[SUB][16];
__device__ float g_INe[SUB][T_DATA];
__device__ float g_INi[SUB][T_DATA];
__device__ float g_syn_s[SUB][T_DATA];
__device__ float g_syn_ns[SUB][T_DATA];

// ---------------- K0: pack connectivity into bitmasks ----------------
__global__ void k_pack(const float* __restrict__ Ce, const float* __restrict__ Ci) {
    int idx = blockIdx.x * blockDim.x + threadIdx.x;
    if (idx < SUB * 64) {
        int s = idx >> 6, m = idx & 63;
        int it = m >> 2, c = m & 3;
        unsigned bits = 0;
        for (int l = 0; l < 32; l++) {
            int e = it * 128 + l * 4 + c;
            if (e < E_NO && Ce[s * E_NO + e] != 0.f) bits |= (1u << l);
        }
        g_mask_e[s][m] = bits;
    } else if (idx < SUB * 64 + SUB * 16) {
        int j = idx - SUB * 64;
        int s = j >> 4, m = j & 15;
        int it = m >> 2, c = m & 3;
        unsigned bits = 0;
        for (int l = 0; l < 32; l++) {
            int e = it * 128 + l * 4 + c;
            if (e < I_NO && Ci[s * I_NO + e] != 0.f) bits |= (1u << l);
        }
        g_mask_i[s][m] = bits;
    }
}

// ---------------- K1: IN = S @ C.T via ballot + popcount (HBM-bound) ----------------
__global__ __launch_bounds__(256) void k_reduce(const float* __restrict__ Se,
                                                const float* __restrict__ Si) {
    __shared__ unsigned sme[64][13];  // [m][s], padded stride 13 -> conflict-free
    __shared__ unsigned smi[16][13];
    for (int i = threadIdx.x; i < SUB * 64; i += blockDim.x)
        sme[i % 64][i / 64] = g_mask_e[i / 64][i % 64];
    for (int i = threadIdx.x; i < SUB * 16; i += blockDim.x)
        smi[i % 16][i / 16] = g_mask_i[i / 16][i % 16];
    __syncthreads();

    int warp = threadIdx.x >> 5, lane = threadIdx.x & 31;
    int row = blockIdx.x * 8 + warp;
    if (row >= T_DATA) return;

    const float* re = Se + (size_t)row * E_NO;
    const float* ri = Si + (size_t)row * I_NO;
    int acc_e = 0, acc_i = 0;

#pragma unroll 4
    for (int it = 0; it < 16; it++) {
        int base = it * 128 + lane * 4;
        float4 v = make_float4(0.f, 0.f, 0.f, 0.f);
        if (base < E_NO) v = *(const float4*)(re + base);   // E_NO % 4 == 0
        unsigned m0 = __ballot_sync(0xffffffffu, v.x != 0.f);
        unsigned m1 = __ballot_sync(0xffffffffu, v.y != 0.f);
        unsigned m2 = __ballot_sync(0xffffffffu, v.z != 0.f);
        unsigned m3 = __ballot_sync(0xffffffffu, v.w != 0.f);
        if (lane < SUB) {
            acc_e += __popc(m0 & sme[it * 4 + 0][lane]);
            acc_e += __popc(m1 & sme[it * 4 + 1][lane]);
            acc_e += __popc(m2 & sme[it * 4 + 2][lane]);
            acc_e += __popc(m3 & sme[it * 4 + 3][lane]);
        }
    }
#pragma unroll
    for (int it = 0; it < 4; it++) {
        int base = it * 128 + lane * 4;
        float4 v = make_float4(0.f, 0.f, 0.f, 0.f);
        if (base < I_NO) v = *(const float4*)(ri + base);   // I_NO % 4 == 0
        unsigned m0 = __ballot_sync(0xffffffffu, v.x != 0.f);
        unsigned m1 = __ballot_sync(0xffffffffu, v.y != 0.f);
        unsigned m2 = __ballot_sync(0xffffffffu, v.z != 0.f);
        unsigned m3 = __ballot_sync(0xffffffffu, v.w != 0.f);
        if (lane < SUB) {
            acc_i += __popc(m0 & smi[it * 4 + 0][lane]);
            acc_i += __popc(m1 & smi[it * 4 + 1][lane]);
            acc_i += __popc(m2 & smi[it * 4 + 2][lane]);
            acc_i += __popc(m3 & smi[it * 4 + 3][lane]);
        }
    }
    if (lane < SUB) {
        g_INe[lane][row] = (float)acc_e;
        g_INi[lane][row] = (float)acc_i;
    }
}

// ---------------- K2: causal 200-tap conv (s and ns kernels, e and i channels) ----------------
__global__ __launch_bounds__(128) void k_conv(const float* __restrict__ Ws_syn,
                                              const float* __restrict__ Wns_syn,
                                              const float* __restrict__ Ds,
                                              const float* __restrict__ Dns) {
    __shared__ float ke_s[NTAP], ki_s[NTAP], ke_ns[NTAP], ki_ns[NTAP];
    __shared__ float sh_e[1024 + NTAP], sh_i[1024 + NTAP];
    const int s = blockIdx.y;
    const int tbase = blockIdx.x * 1024;
    const int tid = threadIdx.x;

    // build synaptic kernels: k[c][t] = sum_b W[s,b,c] * tt * exp(-tt),
    // tt = max(t - exp(Delta[s,c]), 0) / tau_b, tau_b = exp(0.5 b)
    float d_se = expf(Ds[s * 2 + 0]);
    float d_si = expf(Ds[s * 2 + 1]);
    float d_ne = expf(Dns[s * 2 + 0]);
    float d_ni = expf(Dns[s * 2 + 1]);
    const float it0 = 1.f, it1 = 0.60653065971f, it2 = 0.36787944117f;
    for (int k = tid; k < NTAP; k += blockDim.x) {
        float fk = (float)k;
        {
            float u = fmaxf(fk - d_se, 0.f);
            float a = u * it0, b = u * it1, c = u * it2;
            ke_s[k] = Ws_syn[s * 6 + 0] * a * expf(-a) + Ws_syn[s * 6 + 2] * b * expf(-b) +
                      Ws_syn[s * 6 + 4] * c * expf(-c);
        }
        {
            float u = fmaxf(fk - d_si, 0.f);
            float a = u * it0, b = u * it1, c = u * it2;
            ki_s[k] = Ws_syn[s * 6 + 1] * a * expf(-a) + Ws_syn[s * 6 + 3] * b * expf(-b) +
                      Ws_syn[s * 6 + 5] * c * expf(-c);
        }
        {
            float u = fmaxf(fk - d_ne, 0.f);
            float a = u * it0, b = u * it1, c = u * it2;
            ke_ns[k] = Wns_syn[s * 6 + 0] * a * expf(-a) + Wns_syn[s * 6 + 2] * b * expf(-b) +
                       Wns_syn[s * 6 + 4] * c * expf(-c);
        }
        {
            float u = fmaxf(fk - d_ni, 0.f);
            float a = u * it0, b = u * it1, c = u * it2;
            ki_ns[k] = Wns_syn[s * 6 + 1] * a * expf(-a) + Wns_syn[s * 6 + 3] * b * expf(-b) +
                       Wns_syn[s * 6 + 5] * c * expf(-c);
        }
    }
    // load input tile with left halo of NTAP-1
    for (int j = tid; j < 1024 + NTAP; j += blockDim.x) {
        int g = tbase - (NTAP - 1) + j;
        bool in = (g >= 0 && g < T_DATA);
        sh_e[j] = in ? g_INe[s][g] : 0.f;
        sh_i[j] = in ? g_INi[s][g] : 0.f;
    }
    __syncthreads();

    float accs[8], accn[8];
#pragma unroll
    for (int r = 0; r < 8; r++) { accs[r] = 0.f; accn[r] = 0.f; }

#pragma unroll 2
    for (int kk = 0; kk < NTAP; kk++) {
        float ces = ke_s[NTAP - 1 - kk], cis = ki_s[NTAP - 1 - kk];
        float cen = ke_ns[NTAP - 1 - kk], cin = ki_ns[NTAP - 1 - kk];
#pragma unroll
        for (int r = 0; r < 8; r++) {
            float e = sh_e[tid + 128 * r + kk];
            float i = sh_i[tid + 128 * r + kk];
            accs[r] = fmaf(ces, e, accs[r]);
            accs[r] = fmaf(cis, i, accs[r]);
            accn[r] = fmaf(cen, e, accn[r]);
            accn[r] = fmaf(cin, i, accn[r]);
        }
    }
#pragma unroll
    for (int r = 0; r < 8; r++) {
        int t = tbase + tid + 128 * r;
        if (t < T_DATA) {
            g_syn_s[s][t] = accs[r];
            g_syn_ns[s][t] = accn[r];
        }
    }
}

// ---------------- K3: wavefront recurrence + outputs ----------------
// Strictly-lower-triangular C_den => subunit i at time t depends on subunits j<i at t-1.
// Each block covers 244 outputs with a 12-step left halo; 12 levels with __syncthreads.
__device__ __forceinline__ float sigm(float x) { return 1.f / (1.f + __expf(-x)); }

__global__ __launch_bounds__(256) void k_rec(const float* __restrict__ C_den,
                                             const float* __restrict__ Ths_g,
                                             const float* __restrict__ Thns_g,
                                             const float* __restrict__ Ws_g,
                                             const float* __restrict__ Wns_g,
                                             float* __restrict__ out) {
    __shared__ float sig[SUB][256];       // sig[j][lt] = sigmoid(X_ns at step t)
    __shared__ float cwns[SUB][SUB];      // C_den[i][j] * W_ns_sub[j]
    __shared__ float cden[SUB][SUB];
    __shared__ float ths[SUB], thns[SUB], ws[SUB], wns[SUB];

    int tid = threadIdx.x;
    if (tid < SUB * SUB) {
        float c = C_den[tid];
        cden[tid / SUB][tid % SUB] = c;
        cwns[tid / SUB][tid % SUB] = c * Wns_g[tid % SUB];
    }
    if (tid < SUB) {
        ths[tid] = Ths_g[tid];
        thns[tid] = Thns_g[tid];
        ws[tid] = Ws_g[tid];
        wns[tid] = Wns_g[tid];
    }
    __syncthreads();

    const int t0 = blockIdx.x * 244;
    const int t = t0 - 12 + tid;
    const bool tin = (t >= 0 && t < T_DATA);

#pragma unroll
    for (int j = 0; j < SUB; j++) {
        float x = (tin ? g_syn_ns[j][t] : 0.f) + thns[j];
        if (t >= 1 && tid >= 1) {
#pragma unroll
            for (int jj = 0; jj < j; jj++) x += cwns[j][jj] * sig[jj][tid - 1];
        }
        sig[j][tid] = sigm(x);
        __syncthreads();
    }

    if (tid >= 12 && t < T_DATA) {
        float* orow = out + (size_t)t * (3 * SUB - 1);

        float sp[SUB];
#pragma unroll
        for (int j = 0; j < SUB; j++) sp[j] = sig[j][tid];

        // Y_s(t+1): col 0 from s-path sigmoid, cols 1.. from ns-path sigmoid
        float sig_s0 = sigm(g_syn_s[0][t] + ths[0]);
        orow[0] = sig_s0 * ws[0];
#pragma unroll
        for (int j = 1; j < SUB; j++) orow[j] = sp[j] * ws[j];
        // Y_ns(t+1)
#pragma unroll
        for (int j = 0; j < SUB; j++) orow[SUB + j] = sp[j] * wns[j];

        // sig_s[1:]: needs X_s(t) built from the s-carry Y_s(t) (step t-1 output)
        float ysp[SUB];
        if (t >= 1) {
            ysp[0] = sigm(g_syn_s[0][t - 1] + ths[0]) * ws[0];
#pragma unroll
            for (int j = 1; j < SUB; j++) ysp[j] = sig[j][tid - 1] * ws[j];
        } else {
#pragma unroll
            for (int j = 0; j < SUB; j++) ysp[j] = 0.f;
        }
#pragma unroll
        for (int i = 1; i < SUB; i++) {
            float x = g_syn_s[i][t] + ths[i];
#pragma unroll
            for (int jj = 0; jj < i; jj++) x += cden[i][jj] * ysp[jj];
            orow[2 * SUB + (i - 1)] = sigm(x);
        }
    }
}

// ---------------- launcher ----------------
extern "C" void kernel_launch(void* const* d_in, const int* in_sizes, int n_in,
                              void* d_out, int out_size) {
    const float* S_e      = (const float*)d_in[0];
    const float* S_i      = (const float*)d_in[1];
    const float* C_syn_e  = (const float*)d_in[2];
    const float* C_syn_i  = (const float*)d_in[3];
    const float* C_den    = (const float*)d_in[4];
    const float* W_s_syn  = (const float*)d_in[5];
    const float* W_ns_syn = (const float*)d_in[6];
    const float* Delta_s  = (const float*)d_in[7];
    const float* Delta_ns = (const float*)d_in[8];
    const float* Theta_s  = (const float*)d_in[9];
    const float* Theta_ns = (const float*)d_in[10];
    const float* W_s_sub  = (const float*)d_in[11];
    const float* W_ns_sub = (const float*)d_in[12];
    float* out = (float*)d_out;

    k_pack<<<4, 256>>>(C_syn_e, C_syn_i);
    k_reduce<<<T_DATA / 8, 256>>>(S_e, S_i);
    k_conv<<<dim3((T_DATA + 1023) / 1024, SUB), 128>>>(W_s_syn, W_ns_syn, Delta_s, Delta_ns);
    k_rec<<<(T_DATA + 243) / 244, 256>>>(C_den, Theta_s, Theta_ns, W_s_sub, W_ns_sub, out);
}

// round 2
// speedup vs baseline: 1.3873x; 1.3873x over previous
#include <cuda_runtime.h>

#define T_DATA 20000
#define E_NO   2000
#define I_NO   500
#define SUB    12
#define CTAP   72            // effective taps: kernel tail beyond 72 is < 2e-10
#define HALO   (CTAP - 1)

// ---------------- device scratch (static, no allocation) ----------------
__device__ unsigned g_mask_e[SUB][64];   // [s][it*4+c], bit l <-> element it*128 + l*4 + c
__device__ unsigned g_mask_i[SUB][16];
__device__ float g_INe[SUB][T_DATA];
__device__ float g_INi[SUB][T_DATA];
__device__ float g_syn_s[SUB][T_DATA];
__device__ float g_syn_ns[SUB][T_DATA];

// ---------------- K0: pack connectivity into bitmasks (1 warp / word) ----------------
__global__ __launch_bounds__(256) void k_pack(const float* __restrict__ Ce,
                                              const float* __restrict__ Ci) {
    int gt = blockIdx.x * blockDim.x + threadIdx.x;
    int w = gt >> 5, lane = gt & 31;
    if (w < SUB * 64) {
        int s = w >> 6, m = w & 63;
        int it = m >> 2, c = m & 3;
        int e = it * 128 + lane * 4 + c;
        bool b = (e < E_NO) && (Ce[s * E_NO + e] != 0.f);
        unsigned bits = __ballot_sync(0xffffffffu, b);
        if (lane == 0) g_mask_e[s][m] = bits;
    } else if (w < SUB * 64 + SUB * 16) {
        int j = w - SUB * 64;
        int s = j >> 4, m = j & 15;
        int it = m >> 2, c = m & 3;
        int e = it * 128 + lane * 4 + c;
        bool b = (e < I_NO) && (Ci[s * I_NO + e] != 0.f);
        unsigned bits = __ballot_sync(0xffffffffu, b);
        if (lane == 0) g_mask_i[s][m] = bits;
    }
}

// ---------------- K1: IN = S @ C.T via ballot + popcount (HBM-bound) ----------------
__global__ __launch_bounds__(256) void k_reduce(const float* __restrict__ Se,
                                                const float* __restrict__ Si) {
    __shared__ unsigned sme[64][13];  // [m][s], padded -> conflict-free
    __shared__ unsigned smi[16][13];
    for (int i = threadIdx.x; i < SUB * 64; i += blockDim.x)
        sme[i % 64][i / 64] = g_mask_e[i / 64][i % 64];
    for (int i = threadIdx.x; i < SUB * 16; i += blockDim.x)
        smi[i % 16][i / 16] = g_mask_i[i / 16][i % 16];
    __syncthreads();

    int warp = threadIdx.x >> 5, lane = threadIdx.x & 31;
    int row = blockIdx.x * 8 + warp;
    if (row >= T_DATA) return;

    const float* re = Se + (size_t)row * E_NO;
    const float* ri = Si + (size_t)row * I_NO;
    int acc_e = 0, acc_i = 0;

#pragma unroll
    for (int ob = 0; ob < 4; ob++) {
        float4 v[4];
#pragma unroll
        for (int q = 0; q < 4; q++) {
            int base = (ob * 4 + q) * 128 + lane * 4;
            v[q] = (base < E_NO) ? *(const float4*)(re + base)
                                 : make_float4(0.f, 0.f, 0.f, 0.f);
        }
#pragma unroll
        for (int q = 0; q < 4; q++) {
            int it = ob * 4 + q;
            unsigned m0 = __ballot_sync(0xffffffffu, v[q].x != 0.f);
            unsigned m1 = __ballot_sync(0xffffffffu, v[q].y != 0.f);
            unsigned m2 = __ballot_sync(0xffffffffu, v[q].z != 0.f);
            unsigned m3 = __ballot_sync(0xffffffffu, v[q].w != 0.f);
            if (lane < SUB) {
                acc_e += __popc(m0 & sme[it * 4 + 0][lane]);
                acc_e += __popc(m1 & sme[it * 4 + 1][lane]);
                acc_e += __popc(m2 & sme[it * 4 + 2][lane]);
                acc_e += __popc(m3 & sme[it * 4 + 3][lane]);
            }
        }
    }
    {
        float4 v[4];
#pragma unroll
        for (int q = 0; q < 4; q++) {
            int base = q * 128 + lane * 4;
            v[q] = (base < I_NO) ? *(const float4*)(ri + base)
                                 : make_float4(0.f, 0.f, 0.f, 0.f);
        }
#pragma unroll
        for (int q = 0; q < 4; q++) {
            unsigned m0 = __ballot_sync(0xffffffffu, v[q].x != 0.f);
            unsigned m1 = __ballot_sync(0xffffffffu, v[q].y != 0.f);
            unsigned m2 = __ballot_sync(0xffffffffu, v[q].z != 0.f);
            unsigned m3 = __ballot_sync(0xffffffffu, v[q].w != 0.f);
            if (lane < SUB) {
                acc_i += __popc(m0 & smi[q * 4 + 0][lane]);
                acc_i += __popc(m1 & smi[q * 4 + 1][lane]);
                acc_i += __popc(m2 & smi[q * 4 + 2][lane]);
                acc_i += __popc(m3 & smi[q * 4 + 3][lane]);
            }
        }
    }
    if (lane < SUB) {
        g_INe[lane][row] = (float)acc_e;
        g_INi[lane][row] = (float)acc_i;
    }
}

// ---------------- K2: causal conv, 72 taps, 4 outputs/thread, float4 window --------
__global__ __launch_bounds__(128) void k_conv(const float* __restrict__ Ws_syn,
                                              const float* __restrict__ Wns_syn,
                                              const float* __restrict__ Ds,
                                              const float* __restrict__ Dns) {
    __shared__ float ce_s[CTAP], ci_s[CTAP], ce_ns[CTAP], ci_ns[CTAP];  // reversed kernels
    __shared__ __align__(16) float sh_e[512 + CTAP + 4];
    __shared__ __align__(16) float sh_i[512 + CTAP + 4];
    const int s = blockIdx.y;
    const int tbase = blockIdx.x * 512;
    const int tid = threadIdx.x;

    float d_se = expf(Ds[s * 2 + 0]);
    float d_si = expf(Ds[s * 2 + 1]);
    float d_ne = expf(Dns[s * 2 + 0]);
    float d_ni = expf(Dns[s * 2 + 1]);
    const float it0 = 1.f, it1 = 0.60653065971f, it2 = 0.36787944117f;
    for (int k = tid; k < CTAP; k += blockDim.x) {
        float fk = (float)(CTAP - 1 - k);   // store coefficient for lag (CTAP-1-k) at [k]
        {
            float u = fmaxf(fk - d_se, 0.f);
            float a = u * it0, b = u * it1, c = u * it2;
            ce_s[k] = Ws_syn[s * 6 + 0] * a * expf(-a) + Ws_syn[s * 6 + 2] * b * expf(-b) +
                      Ws_syn[s * 6 + 4] * c * expf(-c);
        }
        {
            float u = fmaxf(fk - d_si, 0.f);
            float a = u * it0, b = u * it1, c = u * it2;
            ci_s[k] = Ws_syn[s * 6 + 1] * a * expf(-a) + Ws_syn[s * 6 + 3] * b * expf(-b) +
                      Ws_syn[s * 6 + 5] * c * expf(-c);
        }
        {
            float u = fmaxf(fk - d_ne, 0.f);
            float a = u * it0, b = u * it1, c = u * it2;
            ce_ns[k] = Wns_syn[s * 6 + 0] * a * expf(-a) + Wns_syn[s * 6 + 2] * b * expf(-b) +
                       Wns_syn[s * 6 + 4] * c * expf(-c);
        }
        {
            float u = fmaxf(fk - d_ni, 0.f);
            float a = u * it0, b = u * it1, c = u * it2;
            ci_ns[k] = Wns_syn[s * 6 + 1] * a * expf(-a) + Wns_syn[s * 6 + 3] * b * expf(-b) +
                       Wns_syn[s * 6 + 5] * c * expf(-c);
        }
    }
    for (int j = tid; j < 512 + CTAP; j += blockDim.x) {
        int g = tbase - HALO + j;
        bool in = (g >= 0 && g < T_DATA);
        sh_e[j] = in ? g_INe[s][g] : 0.f;
        sh_i[j] = in ? g_INi[s][g] : 0.f;
    }
    __syncthreads();

    const float4* she4 = (const float4*)sh_e;
    const float4* shi4 = (const float4*)sh_i;

    float accs[4] = {0.f, 0.f, 0.f, 0.f};
    float accn[4] = {0.f, 0.f, 0.f, 0.f};

    float4 Ae = she4[tid];
    float4 Ai = shi4[tid];
#pragma unroll
    for (int kb = 0; kb < CTAP; kb += 4) {
        float4 Be = she4[tid + kb / 4 + 1];
        float4 Bi = shi4[tid + kb / 4 + 1];
        float we[8] = {Ae.x, Ae.y, Ae.z, Ae.w, Be.x, Be.y, Be.z, Be.w};
        float wi[8] = {Ai.x, Ai.y, Ai.z, Ai.w, Bi.x, Bi.y, Bi.z, Bi.w};
#pragma unroll
        for (int u = 0; u < 4; u++) {
            float ces = ce_s[kb + u], cis = ci_s[kb + u];
            float cen = ce_ns[kb + u], cin = ci_ns[kb + u];
#pragma unroll
            for (int r = 0; r < 4; r++) {
                float e = we[u + r];
                float i = wi[u + r];
                accs[r] = fmaf(ces, e, accs[r]);
                accs[r] = fmaf(cis, i, accs[r]);
                accn[r] = fmaf(cen, e, accn[r]);
                accn[r] = fmaf(cin, i, accn[r]);
            }
        }
        Ae = Be;
        Ai = Bi;
    }
#pragma unroll
    for (int r = 0; r < 4; r++) {
        int t = tbase + tid * 4 + r;
        if (t < T_DATA) {
            g_syn_s[s][t] = accs[r];
            g_syn_ns[s][t] = accn[r];
        }
    }
}

// ---------------- K3: warp-shuffle wavefront recurrence + coalesced outputs --------
// Strictly-lower-triangular C_den: sig[j] at lane L exact for L >= j (max j = 11),
// so a 12-lane halo per warp yields 20 exact outputs per warp, zero barriers.
__device__ __forceinline__ float sigm(float x) { return 1.f / (1.f + __expf(-x)); }

__global__ __launch_bounds__(256) void k_rec(const float* __restrict__ C_den,
                                             const float* __restrict__ Ths_g,
                                             const float* __restrict__ Thns_g,
                                             const float* __restrict__ Ws_g,
                                             const float* __restrict__ Wns_g,
                                             float* __restrict__ out) {
    __shared__ float cwns[SUB][SUB];
    __shared__ float cden[SUB][SUB];
    __shared__ float ths[SUB], thns[SUB], ws[SUB], wns[SUB];
    __shared__ __align__(16) float obuf[160 * 35];

    int tid = threadIdx.x, warp = tid >> 5, lane = tid & 31;
    if (tid < SUB * SUB) {
        float c = C_den[tid];
        cden[tid / SUB][tid % SUB] = c;
        cwns[tid / SUB][tid % SUB] = c * Wns_g[tid % SUB];
    }
    if (tid < SUB) {
        ths[tid] = Ths_g[tid];
        thns[tid] = Thns_g[tid];
        ws[tid] = Ws_g[tid];
        wns[tid] = Wns_g[tid];
    }
    __syncthreads();

    const int t = blockIdx.x * 160 + warp * 20 + lane - 12;   // grid 125: max t = 19999
    const bool tin = (t >= 0);
    const bool rec = (t >= 1);

    float sn[SUB], ss[SUB];
#pragma unroll
    for (int j = 0; j < SUB; j++) {
        sn[j] = tin ? g_syn_ns[j][t] : 0.f;
        ss[j] = tin ? g_syn_s[j][t] : 0.f;
    }
    float ssp0 = rec ? g_syn_s[0][t - 1] : 0.f;

    float sig[SUB], sigp[SUB];
#pragma unroll
    for (int j = 0; j < SUB; j++) {
        float r = 0.f;
#pragma unroll
        for (int jj = 0; jj < j; jj++) r += cwns[j][jj] * sigp[jj];
        float x = sn[j] + thns[j] + (rec ? r : 0.f);
        sig[j] = sigm(x);
        sigp[j] = __shfl_up_sync(0xffffffffu, sig[j], 1);
    }

    if (lane >= 12) {
        int lt = warp * 20 + lane - 12;
        float* o = obuf + lt * 35;
        o[0] = sigm(ss[0] + ths[0]) * ws[0];
#pragma unroll
        for (int j = 1; j < SUB; j++) o[j] = sig[j] * ws[j];
#pragma unroll
        for (int j = 0; j < SUB; j++) o[SUB + j] = sig[j] * wns[j];

        float ysp[SUB];
        ysp[0] = rec ? sigm(ssp0 + ths[0]) * ws[0] : 0.f;
#pragma unroll
        for (int j = 1; j < SUB; j++) ysp[j] = rec ? sigp[j] * ws[j] : 0.f;
#pragma unroll
        for (int i = 1; i < SUB; i++) {
            float x = ss[i] + ths[i];
#pragma unroll
            for (int jj = 0; jj < i; jj++) x = fmaf(cden[i][jj], ysp[jj], x);
            o[2 * SUB + (i - 1)] = sigm(x);
        }
    }
    __syncthreads();

    // coalesced copy: 160 rows * 35 floats = 5600 floats = 1400 float4
    const float4* src = (const float4*)obuf;
    float4* dst = (float4*)(out + (size_t)blockIdx.x * 5600);
    for (int i = tid; i < 1400; i += 256) dst[i] = src[i];
}

// ---------------- launcher ----------------
extern "C" void kernel_launch(void* const* d_in, const int* in_sizes, int n_in,
                              void* d_out, int out_size) {
    const float* S_e      = (const float*)d_in[0];
    const float* S_i      = (const float*)d_in[1];
    const float* C_syn_e  = (const float*)d_in[2];
    const float* C_syn_i  = (const float*)d_in[3];
    const float* C_den    = (const float*)d_in[4];
    const float* W_s_syn  = (const float*)d_in[5];
    const float* W_ns_syn = (const float*)d_in[6];
    const float* Delta_s  = (const float*)d_in[7];
    const float* Delta_ns = (const float*)d_in[8];
    const float* Theta_s  = (const float*)d_in[9];
    const float* Theta_ns = (const float*)d_in[10];
    const float* W_s_sub  = (const float*)d_in[11];
    const float* W_ns_sub = (const float*)d_in[12];
    float* out = (float*)d_out;

    k_pack<<<120, 256>>>(C_syn_e, C_syn_i);
    k_reduce<<<T_DATA / 8, 256>>>(S_e, S_i);
    k_conv<<<dim3((T_DATA + 511) / 512, SUB), 128>>>(W_s_syn, W_ns_syn, Delta_s, Delta_ns);
    k_rec<<<125, 256>>>(C_den, Theta_s, Theta_ns, W_s_sub, W_ns_sub, out);
}